// round 1
// baseline (speedup 1.0000x reference)
#include <cuda_runtime.h>

#define BB 4
#define NN 4096
#define MM 4096
#define DD 256

#define TM 128
#define TN 128
#define TK 16
#define PAD 17   // smem row stride in floats (conflict-free for strided r=ty+16m reads)

// Scratch (device globals: allocation-free per harness rules)
__device__ float g_xnorm[BB * NN];
__device__ float g_ynorm[BB * MM];
__device__ float g_partial[BB * 32];

// ---------------------------------------------------------------------------
// Kernel 1: per-row squared norms for source and target (warp per row)
// ---------------------------------------------------------------------------
__global__ void norms_kernel(const float* __restrict__ src,
                             const float* __restrict__ tgt) {
    int warp = (blockIdx.x * blockDim.x + threadIdx.x) >> 5;
    int lane = threadIdx.x & 31;
    const int total = BB * NN + BB * MM;
    if (warp >= total) return;

    const float* base;
    float* outp;
    int row;
    if (warp < BB * NN) { base = src; outp = g_xnorm; row = warp; }
    else                { base = tgt; outp = g_ynorm; row = warp - BB * NN; }

    const float4* p = (const float4*)(base + (long long)row * DD);
    float s = 0.f;
#pragma unroll
    for (int i = 0; i < DD / 4 / 32; ++i) {   // 2 iterations
        float4 v = p[lane + 32 * i];
        s += v.x * v.x + v.y * v.y + v.z * v.z + v.w * v.w;
    }
#pragma unroll
    for (int o = 16; o > 0; o >>= 1) s += __shfl_down_sync(0xffffffffu, s, o);
    if (lane == 0) outp[row] = s;
}

// ---------------------------------------------------------------------------
// Kernel 2: fused GEMM + row-min.  Block = (batch b, 128 source rows).
// Loops over all 4096 targets in 128-wide tiles; 8x8 per-thread microtile.
// Tracks min_j(||y_j||^2 - 2 x.y_j) per row; epilogue adds ||x||^2, clamps.
// ---------------------------------------------------------------------------
__global__ __launch_bounds__(256, 1)
void mincost_kernel(const float* __restrict__ src, const float* __restrict__ tgt) {
    __shared__ float sA[TM * PAD];
    __shared__ float sB[TN * PAD];
    __shared__ float sY[TN];
    __shared__ int   rowMinI[TM];
    __shared__ float red[8];

    const int tid = threadIdx.x;
    const int tx = tid & 15;
    const int ty = tid >> 4;
    const int b  = blockIdx.y;
    const int it = blockIdx.x;

    const float* srcT = src + (long long)b * NN * DD + (long long)it * TM * DD;
    const float* tgtB = tgt + (long long)b * MM * DD;

    if (tid < TM) rowMinI[tid] = 0x7F800000;   // +inf bits

    float rmin[8];
#pragma unroll
    for (int m = 0; m < 8; ++m) rmin[m] = 3.4e38f;

    for (int jt = 0; jt < MM / TN; ++jt) {
        float acc[8][8];
#pragma unroll
        for (int m = 0; m < 8; ++m)
#pragma unroll
            for (int n = 0; n < 8; ++n) acc[m][n] = 0.f;

        const float* tgtT = tgtB + (long long)jt * TN * DD;

        for (int kc = 0; kc < DD / TK; ++kc) {
            __syncthreads();   // previous chunk's compute (and jt's sY fold) done
            // Load 128x16 source chunk and 128x16 target chunk (float4 loads)
            {
                const float4* gp = (const float4*)srcT;
                const float4* gq = (const float4*)tgtT;
#pragma unroll
                for (int u = 0; u < 2; ++u) {
                    int idx = tid + 256 * u;         // 0..511
                    int r   = idx >> 2;
                    int c4  = idx & 3;
                    float4 v = gp[(long long)r * (DD / 4) + kc * 4 + c4];
                    float* d = &sA[r * PAD + c4 * 4];
                    d[0] = v.x; d[1] = v.y; d[2] = v.z; d[3] = v.w;
                    float4 w = gq[(long long)r * (DD / 4) + kc * 4 + c4];
                    float* e = &sB[r * PAD + c4 * 4];
                    e[0] = w.x; e[1] = w.y; e[2] = w.z; e[3] = w.w;
                }
            }
            if (kc == 0 && tid < TN) sY[tid] = g_ynorm[b * MM + jt * TN + tid];
            __syncthreads();

#pragma unroll
            for (int k = 0; k < TK; ++k) {
                float a[8], bb[8];
#pragma unroll
                for (int m = 0; m < 8; ++m) a[m]  = sA[(ty + 16 * m) * PAD + k];
#pragma unroll
                for (int n = 0; n < 8; ++n) bb[n] = sB[(tx + 16 * n) * PAD + k];
#pragma unroll
                for (int m = 0; m < 8; ++m)
#pragma unroll
                    for (int n = 0; n < 8; ++n)
                        acc[m][n] = fmaf(a[m], bb[n], acc[m][n]);
            }
        }

        // Fold this target tile into running row minima (reads sY; safe: next
        // overwrite of sY happens only after the __syncthreads at loop top).
#pragma unroll
        for (int n = 0; n < 8; ++n) {
            float yv = sY[tx + 16 * n];
#pragma unroll
            for (int m = 0; m < 8; ++m) {
                float v = yv - 2.0f * acc[m][n];
                rmin[m] = fminf(rmin[m], v);
            }
        }
    }

    // Epilogue: add ||x||^2, clamp, cross-thread min per row (nonneg floats
    // order-preserve as ints -> atomicMin on int bits is exact).
    const float* xn = &g_xnorm[b * NN + it * TM];
#pragma unroll
    for (int m = 0; m < 8; ++m) {
        int r = ty + 16 * m;
        float cand = fmaxf(xn[r] + rmin[m], 0.0f);
        atomicMin(&rowMinI[r], __float_as_int(cand));
    }
    __syncthreads();

    float s = (tid < TM) ? __int_as_float(rowMinI[tid]) : 0.0f;
#pragma unroll
    for (int o = 16; o > 0; o >>= 1) s += __shfl_down_sync(0xffffffffu, s, o);
    if ((tid & 31) == 0) red[tid >> 5] = s;
    __syncthreads();
    if (tid == 0) {
        float t = 0.f;
#pragma unroll
        for (int w = 0; w < 8; ++w) t += red[w];
        g_partial[b * 32 + it] = t;
    }
}

// ---------------------------------------------------------------------------
// Kernel 3: deterministic finalize (sum 32 block partials per batch, /N)
// ---------------------------------------------------------------------------
__global__ void finalize_kernel(float* __restrict__ out) {
    int b = threadIdx.x;
    if (b < BB) {
        float s = 0.f;
        for (int i = 0; i < 32; ++i) s += g_partial[b * 32 + i];
        out[b] = s * (1.0f / (float)NN);
    }
}

extern "C" void kernel_launch(void* const* d_in, const int* in_sizes, int n_in,
                              void* d_out, int out_size) {
    const float* src = (const float*)d_in[0];
    const float* tgt = (const float*)d_in[1];
    float* out = (float*)d_out;

    // 32768 rows total, one warp per row -> 1,048,576 threads
    norms_kernel<<<(BB * (NN + MM) * 32 + 255) / 256, 256>>>(src, tgt);

    dim3 grid(NN / TM, BB);   // 32 x 4 = 128 blocks
    mincost_kernel<<<grid, 256>>>(src, tgt);

    finalize_kernel<<<1, 32>>>(out);
}

// round 5
// speedup vs baseline: 9.9785x; 9.9785x over previous
#include <cuda_runtime.h>
#include <cuda_bf16.h>
#include <cstdint>

#define BB 4
#define NN 4096
#define MM 4096
#define DD 256

#define TN 64
#define HALF (MM/2)          // 2048 targets per CTA
#define NTILES (HALF/TN)     // 32 target tiles per CTA

#define ASTRIDE 528                         // smem row stride bytes (264 bf16, +16B pad)
#define OFF_A 0
#define A_BYTES (256 * ASTRIDE)             // 135168
#define OFF_B A_BYTES
#define BBUF (64 * ASTRIDE)                 // 33792 per buffer
#define OFF_YN (OFF_B + 2 * BBUF)           // 202752
#define SMEM_TOTAL (OFF_YN + 512)           // 203264 B

// ---------------- device scratch (no allocs allowed) ----------------
__device__ __nv_bfloat16 g_xb16[BB * NN * DD];   // 8 MB
__device__ __nv_bfloat16 g_yb16[BB * MM * DD];   // 8 MB
__device__ float g_xnorm[BB * NN];
__device__ float g_ynorm[BB * MM];
__device__ int   g_rowmin[BB * NN];

// ---------------- helpers (all plain-sm_100-compatible) ----------------
__device__ __forceinline__ uint32_t smem_u32(const void* p) {
    uint32_t a;
    asm("{ .reg .u64 t; cvta.to.shared.u64 t, %1; cvt.u32.u64 %0, t; }"
        : "=r"(a) : "l"(p));
    return a;
}
__device__ __forceinline__ void cp_async16(uint32_t dst, const void* src) {
    asm volatile("cp.async.cg.shared.global [%0], [%1], 16;" :: "r"(dst), "l"(src));
}
__device__ __forceinline__ void cp_async4(uint32_t dst, const void* src) {
    asm volatile("cp.async.ca.shared.global [%0], [%1], 4;" :: "r"(dst), "l"(src));
}
__device__ __forceinline__ void ldm_x4(uint32_t* r, uint32_t addr) {
    asm volatile("ldmatrix.sync.aligned.m8n8.x4.shared.b16 {%0,%1,%2,%3}, [%4];"
        : "=r"(r[0]), "=r"(r[1]), "=r"(r[2]), "=r"(r[3]) : "r"(addr));
}
__device__ __forceinline__ void mma16816(float* c, const uint32_t* a,
                                         uint32_t b0, uint32_t b1) {
    asm volatile(
        "mma.sync.aligned.m16n8k16.row.col.f32.bf16.bf16.f32 "
        "{%0,%1,%2,%3}, {%4,%5,%6,%7}, {%8,%9}, {%0,%1,%2,%3};"
        : "+f"(c[0]), "+f"(c[1]), "+f"(c[2]), "+f"(c[3])
        : "r"(a[0]), "r"(a[1]), "r"(a[2]), "r"(a[3]), "r"(b0), "r"(b1));
}

// ---------------------------------------------------------------------------
// Kernel 1: fp32 -> bf16 conversion + exact fp32 row norms (warp per row)
// ---------------------------------------------------------------------------
__global__ void prep_kernel(const float* __restrict__ src,
                            const float* __restrict__ tgt) {
    int warp = (blockIdx.x * blockDim.x + threadIdx.x) >> 5;
    int lane = threadIdx.x & 31;
    const int total = BB * NN + BB * MM;
    if (warp >= total) return;

    const float* base; __nv_bfloat16* obase; float* onorm; int row;
    if (warp < BB * NN) { base = src; obase = g_xb16; onorm = g_xnorm; row = warp; }
    else                { base = tgt; obase = g_yb16; onorm = g_ynorm; row = warp - BB * NN; }

    const float4* p = (const float4*)(base + (long long)row * DD);
    float4 v0 = p[2 * lane];
    float4 v1 = p[2 * lane + 1];
    float s = v0.x * v0.x + v0.y * v0.y + v0.z * v0.z + v0.w * v0.w
            + v1.x * v1.x + v1.y * v1.y + v1.z * v1.z + v1.w * v1.w;

    __nv_bfloat162 h0 = __floats2bfloat162_rn(v0.x, v0.y);
    __nv_bfloat162 h1 = __floats2bfloat162_rn(v0.z, v0.w);
    __nv_bfloat162 h2 = __floats2bfloat162_rn(v1.x, v1.y);
    __nv_bfloat162 h3 = __floats2bfloat162_rn(v1.z, v1.w);
    uint4 o;
    o.x = *(uint32_t*)&h0; o.y = *(uint32_t*)&h1;
    o.z = *(uint32_t*)&h2; o.w = *(uint32_t*)&h3;
    ((uint4*)(obase + (long long)row * DD))[lane] = o;

#pragma unroll
    for (int off = 16; off > 0; off >>= 1) s += __shfl_down_sync(0xffffffffu, s, off);
    if (lane == 0) onorm[row] = s;
}

// ---------------------------------------------------------------------------
// Kernel 2: init row-min array to +inf bits
// ---------------------------------------------------------------------------
__global__ void init_kernel() {
    int i = blockIdx.x * blockDim.x + threadIdx.x;
    if (i < BB * NN) g_rowmin[i] = 0x7F800000;
}

// ---------------------------------------------------------------------------
// Kernel 3: bf16 HMMA (mma.sync.m16n8k16) GEMM fused with row-min.
// CTA = 256 source rows (A resident in smem) x 2048 targets (32 tiles of 64,
// cp.async double-buffered). 8 warps, 4(M) x 2(N), warp tile 64x32.
// grid (32, 4) = 128 CTAs.
// ---------------------------------------------------------------------------
__global__ __launch_bounds__(256, 1)
void mincost_kernel() {
    extern __shared__ __align__(1024) char smem[];
    uint32_t sb = smem_u32(smem);
    const int tid  = threadIdx.x;
    const int w    = tid >> 5;
    const int lane = tid & 31;
    const int b    = blockIdx.y;
    const int mgrp = blockIdx.x >> 1;
    const int half = blockIdx.x & 1;
    const int base_row = mgrp * 256;
    const int warpM = w >> 1;          // 0..3 (64 rows each)
    const int warpN = w & 1;           // 0..1 (32 cols each)
    const int groupID = lane >> 2;     // 0..7
    const int tig     = lane & 3;      // 0..3

    const __nv_bfloat16* xa  = g_xb16 + ((long long)b * NN + base_row) * DD;
    const __nv_bfloat16* yb  = g_yb16 + ((long long)b * MM + half * HALF) * DD;
    const float*         yng = g_ynorm + b * MM + half * HALF;

    // Issue A (256 rows) + B tile 0 + yn0 as cp.async group 0
#pragma unroll
    for (int u = 0; u < 32; ++u) {
        int c = tid + 256 * u;          // 8192 chunks of 16B
        int r = c >> 5, c16 = c & 31;
        cp_async16(sb + OFF_A + r * ASTRIDE + c16 * 16, xa + r * DD + c16 * 8);
    }
#pragma unroll
    for (int u = 0; u < 8; ++u) {
        int c = tid + 256 * u;          // 2048 chunks
        int r = c >> 5, c16 = c & 31;
        cp_async16(sb + OFF_B + r * ASTRIDE + c16 * 16, yb + r * DD + c16 * 8);
    }
    if (tid < TN) cp_async4(sb + OFF_YN + tid * 4, yng + tid);
    asm volatile("cp.async.commit_group;");

    // ldmatrix per-thread base addresses
    // A x4 for mfrag mf: lanes 0-15 -> rows (lane&15), lanes 16-31 -> +16B col
    uint32_t aBase = sb + OFF_A + (uint32_t)(warpM * 64 + (lane & 15)) * ASTRIDE
                   + (uint32_t)((lane >> 4) * 16);
    // B x4 for nfrag pair p: n = warpN*32 + p*16 + (lane&7) + ((lane>>4)&1)*8,
    // col byte = ((lane>>3)&1)*16
    uint32_t bBase = sb + OFF_B
                   + (uint32_t)(warpN * 32 + (lane & 7) + ((lane >> 4) & 1) * 8) * ASTRIDE
                   + (uint32_t)(((lane >> 3) & 1) * 16);

    float rmin[8];
#pragma unroll
    for (int i = 0; i < 8; ++i) rmin[i] = 3.4e38f;

    for (int jt = 0; jt < NTILES; ++jt) {
        const int s = jt & 1;

        if (jt + 1 < NTILES) {
            const __nv_bfloat16* yt = yb + (long long)(jt + 1) * TN * DD;
            uint32_t dstb = sb + OFF_B + (uint32_t)(s ^ 1) * BBUF;
#pragma unroll
            for (int u = 0; u < 8; ++u) {
                int c = tid + 256 * u;
                int r = c >> 5, c16 = c & 31;
                cp_async16(dstb + r * ASTRIDE + c16 * 16, yt + r * DD + c16 * 8);
            }
            if (tid < TN)
                cp_async4(sb + OFF_YN + (s ^ 1) * 256 + tid * 4,
                          yng + (jt + 1) * TN + tid);
            asm volatile("cp.async.commit_group;");
            asm volatile("cp.async.wait_group 1;");   // tile jt resident
        } else {
            asm volatile("cp.async.wait_group 0;");
        }
        __syncthreads();

        float acc[4][4][4];
#pragma unroll
        for (int mf = 0; mf < 4; ++mf)
#pragma unroll
            for (int nf = 0; nf < 4; ++nf)
#pragma unroll
                for (int i = 0; i < 4; ++i) acc[mf][nf][i] = 0.0f;

        const uint32_t bB = bBase + (uint32_t)s * BBUF;
#pragma unroll
        for (int k = 0; k < 16; ++k) {
            uint32_t afr[4][4], bfr[2][4];
#pragma unroll
            for (int mf = 0; mf < 4; ++mf)
                ldm_x4(afr[mf], aBase + (uint32_t)(mf * 16) * ASTRIDE + k * 32);
#pragma unroll
            for (int p = 0; p < 2; ++p)
                ldm_x4(bfr[p], bB + (uint32_t)(p * 16) * ASTRIDE + k * 32);
#pragma unroll
            for (int mf = 0; mf < 4; ++mf)
#pragma unroll
                for (int nf = 0; nf < 4; ++nf)
                    mma16816(acc[mf][nf], afr[mf],
                             bfr[nf >> 1][(nf & 1) * 2],
                             bfr[nf >> 1][(nf & 1) * 2 + 1]);
        }

        // Fold tile into running per-thread row minima
        const float* ynp = (const float*)(smem + OFF_YN + s * 256);
#pragma unroll
        for (int nf = 0; nf < 4; ++nf) {
            float y0 = ynp[warpN * 32 + nf * 8 + tig * 2];
            float y1 = ynp[warpN * 32 + nf * 8 + tig * 2 + 1];
#pragma unroll
            for (int mf = 0; mf < 4; ++mf) {
                rmin[mf * 2] = fminf(rmin[mf * 2],
                    fminf(fmaf(-2.0f, acc[mf][nf][0], y0),
                          fmaf(-2.0f, acc[mf][nf][1], y1)));
                rmin[mf * 2 + 1] = fminf(rmin[mf * 2 + 1],
                    fminf(fmaf(-2.0f, acc[mf][nf][2], y0),
                          fmaf(-2.0f, acc[mf][nf][3], y1)));
            }
        }
        __syncthreads();   // all reads of buffer s / yn[s] done before reuse
    }

    // Reduce across the 4 threads sharing each row (tig 0..3), then writeback
#pragma unroll
    for (int i = 0; i < 8; ++i) {
        rmin[i] = fminf(rmin[i], __shfl_xor_sync(0xffffffffu, rmin[i], 1));
        rmin[i] = fminf(rmin[i], __shfl_xor_sync(0xffffffffu, rmin[i], 2));
    }
    if (tig == 0) {
#pragma unroll
        for (int mf = 0; mf < 4; ++mf)
#pragma unroll
            for (int h = 0; h < 2; ++h) {
                int row = base_row + warpM * 64 + mf * 16 + h * 8 + groupID;
                float xn = g_xnorm[b * NN + row];
                float cand = fmaxf(xn + rmin[mf * 2 + h], 0.0f);
                atomicMin(&g_rowmin[b * NN + row], __float_as_int(cand));
            }
    }
}

// ---------------------------------------------------------------------------
// Kernel 4: deterministic finalize (mean of row minima per batch)
// ---------------------------------------------------------------------------
__global__ void finalize_kernel(float* __restrict__ out) {
    __shared__ float red[8];
    int b = blockIdx.x;
    int tid = threadIdx.x;
    float s = 0.0f;
    for (int i = tid; i < NN; i += 256)
        s += __int_as_float(g_rowmin[b * NN + i]);
#pragma unroll
    for (int o = 16; o > 0; o >>= 1) s += __shfl_down_sync(0xffffffffu, s, o);
    if ((tid & 31) == 0) red[tid >> 5] = s;
    __syncthreads();
    if (tid == 0) {
        float t = 0.0f;
#pragma unroll
        for (int wv = 0; wv < 8; ++wv) t += red[wv];
        out[b] = t * (1.0f / (float)NN);
    }
}

// ---------------------------------------------------------------------------
extern "C" void kernel_launch(void* const* d_in, const int* in_sizes, int n_in,
                              void* d_out, int out_size) {
    const float* src = (const float*)d_in[0];
    const float* tgt = (const float*)d_in[1];
    float* out = (float*)d_out;

    cudaFuncSetAttribute(mincost_kernel,
                         cudaFuncAttributeMaxDynamicSharedMemorySize, SMEM_TOTAL);

    prep_kernel<<<BB * (NN + MM) / 8, 256>>>(src, tgt);
    init_kernel<<<(BB * NN + 255) / 256, 256>>>();
    mincost_kernel<<<dim3(32, 4), 256, SMEM_TOTAL>>>();
    finalize_kernel<<<BB, 256>>>(out);
}

// round 6
// speedup vs baseline: 10.1599x; 1.0182x over previous
#include <cuda_runtime.h>
#include <cuda_bf16.h>
#include <cstdint>

#define BB 4
#define NN 4096
#define MM 4096
#define DD 256

#define TN 64
#define HALF (MM/2)          // 2048 targets per CTA
#define NTILES (HALF/TN)     // 32 target tiles per CTA

#define ASTRIDE 528                         // smem row stride bytes (264 bf16, +16B pad)
#define OFF_A 0
#define A_BYTES (256 * ASTRIDE)             // 135168
#define OFF_B A_BYTES
#define BBUF (64 * ASTRIDE)                 // 33792 per buffer
#define OFF_YN (OFF_B + 2 * BBUF)           // 202752
#define SMEM_TOTAL (OFF_YN + 512)           // 203264 B

// ---------------- device scratch (no allocs allowed) ----------------
__device__ __nv_bfloat16 g_xb16[BB * NN * DD];   // 8 MB
__device__ __nv_bfloat16 g_yb16[BB * MM * DD];   // 8 MB
__device__ float g_xnorm[BB * NN];
__device__ float g_ynorm[BB * MM];
__device__ int   g_rowmin[BB * NN];
__device__ int   g_done[BB];

// ---------------- helpers (all plain-sm_100-compatible) ----------------
__device__ __forceinline__ uint32_t smem_u32(const void* p) {
    uint32_t a;
    asm("{ .reg .u64 t; cvta.to.shared.u64 t, %1; cvt.u32.u64 %0, t; }"
        : "=r"(a) : "l"(p));
    return a;
}
__device__ __forceinline__ void cp_async16(uint32_t dst, const void* src) {
    asm volatile("cp.async.cg.shared.global [%0], [%1], 16;" :: "r"(dst), "l"(src));
}
__device__ __forceinline__ void cp_async4(uint32_t dst, const void* src) {
    asm volatile("cp.async.ca.shared.global [%0], [%1], 4;" :: "r"(dst), "l"(src));
}
__device__ __forceinline__ void ldm_x4(uint32_t* r, uint32_t addr) {
    asm volatile("ldmatrix.sync.aligned.m8n8.x4.shared.b16 {%0,%1,%2,%3}, [%4];"
        : "=r"(r[0]), "=r"(r[1]), "=r"(r[2]), "=r"(r[3]) : "r"(addr));
}
__device__ __forceinline__ void mma16816(float* c, const uint32_t* a,
                                         uint32_t b0, uint32_t b1) {
    asm volatile(
        "mma.sync.aligned.m16n8k16.row.col.f32.bf16.bf16.f32 "
        "{%0,%1,%2,%3}, {%4,%5,%6,%7}, {%8,%9}, {%0,%1,%2,%3};"
        : "+f"(c[0]), "+f"(c[1]), "+f"(c[2]), "+f"(c[3])
        : "r"(a[0]), "r"(a[1]), "r"(a[2]), "r"(a[3]), "r"(b0), "r"(b1));
}

// ---------------------------------------------------------------------------
// Kernel 1: fp32 -> bf16 conversion + exact fp32 row norms (warp per row).
// Also: x-rows init g_rowmin to +inf; block 0 resets per-batch tickets.
// ---------------------------------------------------------------------------
__global__ void prep_kernel(const float* __restrict__ src,
                            const float* __restrict__ tgt) {
    int warp = (blockIdx.x * blockDim.x + threadIdx.x) >> 5;
    int lane = threadIdx.x & 31;
    if (blockIdx.x == 0 && threadIdx.x < BB) g_done[threadIdx.x] = 0;
    const int total = BB * NN + BB * MM;
    if (warp >= total) return;

    const float* base; __nv_bfloat16* obase; float* onorm; int row;
    bool isx = warp < BB * NN;
    if (isx) { base = src; obase = g_xb16; onorm = g_xnorm; row = warp; }
    else     { base = tgt; obase = g_yb16; onorm = g_ynorm; row = warp - BB * NN; }

    const float4* p = (const float4*)(base + (long long)row * DD);
    float4 v0 = p[2 * lane];
    float4 v1 = p[2 * lane + 1];
    float s = v0.x * v0.x + v0.y * v0.y + v0.z * v0.z + v0.w * v0.w
            + v1.x * v1.x + v1.y * v1.y + v1.z * v1.z + v1.w * v1.w;

    __nv_bfloat162 h0 = __floats2bfloat162_rn(v0.x, v0.y);
    __nv_bfloat162 h1 = __floats2bfloat162_rn(v0.z, v0.w);
    __nv_bfloat162 h2 = __floats2bfloat162_rn(v1.x, v1.y);
    __nv_bfloat162 h3 = __floats2bfloat162_rn(v1.z, v1.w);
    uint4 o;
    o.x = *(uint32_t*)&h0; o.y = *(uint32_t*)&h1;
    o.z = *(uint32_t*)&h2; o.w = *(uint32_t*)&h3;
    ((uint4*)(obase + (long long)row * DD))[lane] = o;

#pragma unroll
    for (int off = 16; off > 0; off >>= 1) s += __shfl_down_sync(0xffffffffu, s, off);
    if (lane == 0) {
        onorm[row] = s;
        if (isx) g_rowmin[row] = 0x7F800000;   // +inf bits
    }
}

// ---------------------------------------------------------------------------
// Kernel 2: bf16 HMMA (mma.sync.m16n8k16) GEMM fused with row-min.
// CTA = 256 source rows (A resident in smem) x 2048 targets (32 tiles of 64,
// cp.async double-buffered). 8 warps, 4(M) x 2(N), warp tile 64x32.
// grid (32, 4) = 128 CTAs. Last CTA per batch reduces the batch mean.
// ---------------------------------------------------------------------------
__global__ __launch_bounds__(256, 1)
void mincost_kernel(float* __restrict__ out) {
    extern __shared__ __align__(1024) char smem[];
    __shared__ int ticket_s;
    __shared__ float red_s[8];
    uint32_t sb = smem_u32(smem);
    const int tid  = threadIdx.x;
    const int w    = tid >> 5;
    const int lane = tid & 31;
    const int b    = blockIdx.y;
    const int mgrp = blockIdx.x >> 1;
    const int half = blockIdx.x & 1;
    const int base_row = mgrp * 256;
    const int warpM = w >> 1;          // 0..3 (64 rows each)
    const int warpN = w & 1;           // 0..1 (32 cols each)
    const int groupID = lane >> 2;     // 0..7
    const int tig     = lane & 3;      // 0..3

    const __nv_bfloat16* xa  = g_xb16 + ((long long)b * NN + base_row) * DD;
    const __nv_bfloat16* yb  = g_yb16 + ((long long)b * MM + half * HALF) * DD;
    const float*         yng = g_ynorm + b * MM + half * HALF;

    // Issue A (256 rows) + B tile 0 + yn0 as cp.async group 0
#pragma unroll
    for (int u = 0; u < 32; ++u) {
        int c = tid + 256 * u;          // 8192 chunks of 16B
        int r = c >> 5, c16 = c & 31;
        cp_async16(sb + OFF_A + r * ASTRIDE + c16 * 16, xa + r * DD + c16 * 8);
    }
#pragma unroll
    for (int u = 0; u < 8; ++u) {
        int c = tid + 256 * u;          // 2048 chunks
        int r = c >> 5, c16 = c & 31;
        cp_async16(sb + OFF_B + r * ASTRIDE + c16 * 16, yb + r * DD + c16 * 8);
    }
    if (tid < TN) cp_async4(sb + OFF_YN + tid * 4, yng + tid);
    asm volatile("cp.async.commit_group;");

    // ldmatrix per-thread base addresses
    uint32_t aBase = sb + OFF_A + (uint32_t)(warpM * 64 + (lane & 15)) * ASTRIDE
                   + (uint32_t)((lane >> 4) * 16);
    uint32_t bBase = sb + OFF_B
                   + (uint32_t)(warpN * 32 + (lane & 7) + ((lane >> 4) & 1) * 8) * ASTRIDE
                   + (uint32_t)(((lane >> 3) & 1) * 16);

    float rmin[8];
#pragma unroll
    for (int i = 0; i < 8; ++i) rmin[i] = 3.4e38f;

    for (int jt = 0; jt < NTILES; ++jt) {
        const int s = jt & 1;

        if (jt + 1 < NTILES) {
            const __nv_bfloat16* yt = yb + (long long)(jt + 1) * TN * DD;
            uint32_t dstb = sb + OFF_B + (uint32_t)(s ^ 1) * BBUF;
#pragma unroll
            for (int u = 0; u < 8; ++u) {
                int c = tid + 256 * u;
                int r = c >> 5, c16 = c & 31;
                cp_async16(dstb + r * ASTRIDE + c16 * 16, yt + r * DD + c16 * 8);
            }
            if (tid < TN)
                cp_async4(sb + OFF_YN + (s ^ 1) * 256 + tid * 4,
                          yng + (jt + 1) * TN + tid);
            asm volatile("cp.async.commit_group;");
            asm volatile("cp.async.wait_group 1;");   // tile jt resident
        } else {
            asm volatile("cp.async.wait_group 0;");
        }
        __syncthreads();

        float acc[4][4][4];
#pragma unroll
        for (int mf = 0; mf < 4; ++mf)
#pragma unroll
            for (int nf = 0; nf < 4; ++nf)
#pragma unroll
                for (int i = 0; i < 4; ++i) acc[mf][nf][i] = 0.0f;

        const uint32_t bB = bBase + (uint32_t)s * BBUF;
#pragma unroll
        for (int k = 0; k < 16; ++k) {
            uint32_t afr[4][4], bfr[2][4];
#pragma unroll
            for (int mf = 0; mf < 4; ++mf)
                ldm_x4(afr[mf], aBase + (uint32_t)(mf * 16) * ASTRIDE + k * 32);
#pragma unroll
            for (int p = 0; p < 2; ++p)
                ldm_x4(bfr[p], bB + (uint32_t)(p * 16) * ASTRIDE + k * 32);
#pragma unroll
            for (int mf = 0; mf < 4; ++mf)
#pragma unroll
                for (int nf = 0; nf < 4; ++nf)
                    mma16816(acc[mf][nf], afr[mf],
                             bfr[nf >> 1][(nf & 1) * 2],
                             bfr[nf >> 1][(nf & 1) * 2 + 1]);
        }

        // Fold tile into running per-thread row minima
        const float* ynp = (const float*)(smem + OFF_YN + s * 256);
#pragma unroll
        for (int nf = 0; nf < 4; ++nf) {
            float y0 = ynp[warpN * 32 + nf * 8 + tig * 2];
            float y1 = ynp[warpN * 32 + nf * 8 + tig * 2 + 1];
#pragma unroll
            for (int mf = 0; mf < 4; ++mf) {
                rmin[mf * 2] = fminf(rmin[mf * 2],
                    fminf(fmaf(-2.0f, acc[mf][nf][0], y0),
                          fmaf(-2.0f, acc[mf][nf][1], y1)));
                rmin[mf * 2 + 1] = fminf(rmin[mf * 2 + 1],
                    fminf(fmaf(-2.0f, acc[mf][nf][2], y0),
                          fmaf(-2.0f, acc[mf][nf][3], y1)));
            }
        }
        __syncthreads();   // all reads of buffer s / yn[s] done before reuse
    }

    // Reduce across the 4 threads sharing each row, then global atomicMin
#pragma unroll
    for (int i = 0; i < 8; ++i) {
        rmin[i] = fminf(rmin[i], __shfl_xor_sync(0xffffffffu, rmin[i], 1));
        rmin[i] = fminf(rmin[i], __shfl_xor_sync(0xffffffffu, rmin[i], 2));
    }
    if (tig == 0) {
#pragma unroll
        for (int mf = 0; mf < 4; ++mf)
#pragma unroll
            for (int h = 0; h < 2; ++h) {
                int row = base_row + warpM * 64 + mf * 16 + h * 8 + groupID;
                float xn = g_xnorm[b * NN + row];
                float cand = fmaxf(xn + rmin[mf * 2 + h], 0.0f);
                atomicMin(&g_rowmin[b * NN + row], __float_as_int(cand));
            }
    }

    // ----- ticketed tail: last CTA of this batch computes the batch mean -----
    __threadfence();           // publish atomicMin results
    __syncthreads();           // all warps' writebacks issued
    if (tid == 0) ticket_s = atomicAdd(&g_done[b], 1);
    __syncthreads();
    if (ticket_s == 2 * (NN / 256) - 1) {     // 31: all 32 CTAs of batch b done
        __threadfence();       // acquire: see all other CTAs' minima
        const int4* p = (const int4*)(g_rowmin + b * NN);
        float s = 0.0f;
        for (int i = tid; i < NN / 4; i += 256) {
            int4 v = p[i];
            s += __int_as_float(v.x) + __int_as_float(v.y)
               + __int_as_float(v.z) + __int_as_float(v.w);
        }
#pragma unroll
        for (int o = 16; o > 0; o >>= 1) s += __shfl_down_sync(0xffffffffu, s, o);
        if (lane == 0) red_s[w] = s;
        __syncthreads();
        if (tid == 0) {
            float t = 0.0f;
#pragma unroll
            for (int wv = 0; wv < 8; ++wv) t += red_s[wv];
            out[b] = t * (1.0f / (float)NN);
        }
    }
}

// ---------------------------------------------------------------------------
extern "C" void kernel_launch(void* const* d_in, const int* in_sizes, int n_in,
                              void* d_out, int out_size) {
    const float* src = (const float*)d_in[0];
    const float* tgt = (const float*)d_in[1];
    float* out = (float*)d_out;

    cudaFuncSetAttribute(mincost_kernel,
                         cudaFuncAttributeMaxDynamicSharedMemorySize, SMEM_TOTAL);

    prep_kernel<<<BB * (NN + MM) / 8, 256>>>(src, tgt);
    mincost_kernel<<<dim3(32, 4), 256, SMEM_TOTAL>>>(out);
}

// round 8
// speedup vs baseline: 10.3122x; 1.0150x over previous
#include <cuda_runtime.h>
#include <cuda_bf16.h>
#include <cstdint>

#define BB 4
#define NN 4096
#define MM 4096
#define DD 256

#define TN 64
#define HALF (MM/2)          // 2048 targets per CTA
#define NTILES (HALF/TN)     // 32 target tiles per CTA

#define ASTRIDE 528                         // smem row stride bytes (264 bf16, +16B pad)
#define OFF_A 0
#define A_BYTES (256 * ASTRIDE)             // 135168
#define OFF_B A_BYTES
#define BBUF (64 * ASTRIDE)                 // 33792 per buffer
#define OFF_YN (OFF_B + 2 * BBUF)           // 202752
#define SMEM_TOTAL (OFF_YN + 512)           // 203264 B

// ---------------- device scratch (no allocs allowed) ----------------
__device__ __nv_bfloat16 g_xb16[BB * NN * DD];   // 8 MB
__device__ __nv_bfloat16 g_yb16[BB * MM * DD];   // 8 MB
__device__ float g_xnorm[BB * NN];
__device__ float g_ynorm[BB * MM];
__device__ int   g_rowmin[BB * NN];
__device__ int   g_done[BB];

// ---------------- helpers (all plain-sm_100-compatible) ----------------
__device__ __forceinline__ uint32_t smem_u32(const void* p) {
    uint32_t a;
    asm("{ .reg .u64 t; cvta.to.shared.u64 t, %1; cvt.u32.u64 %0, t; }"
        : "=r"(a) : "l"(p));
    return a;
}
__device__ __forceinline__ void cp_async16(uint32_t dst, const void* src) {
    asm volatile("cp.async.cg.shared.global [%0], [%1], 16;" :: "r"(dst), "l"(src));
}
__device__ __forceinline__ void cp_async4(uint32_t dst, const void* src) {
    asm volatile("cp.async.ca.shared.global [%0], [%1], 4;" :: "r"(dst), "l"(src));
}
__device__ __forceinline__ void ldm_x4(uint32_t* r, uint32_t addr) {
    asm volatile("ldmatrix.sync.aligned.m8n8.x4.shared.b16 {%0,%1,%2,%3}, [%4];"
        : "=r"(r[0]), "=r"(r[1]), "=r"(r[2]), "=r"(r[3]) : "r"(addr));
}
__device__ __forceinline__ void mma16816(float* c, const uint32_t* a,
                                         uint32_t b0, uint32_t b1) {
    asm volatile(
        "mma.sync.aligned.m16n8k16.row.col.f32.bf16.bf16.f32 "
        "{%0,%1,%2,%3}, {%4,%5,%6,%7}, {%8,%9}, {%0,%1,%2,%3};"
        : "+f"(c[0]), "+f"(c[1]), "+f"(c[2]), "+f"(c[3])
        : "r"(a[0]), "r"(a[1]), "r"(a[2]), "r"(a[3]), "r"(b0), "r"(b1));
}

// ---------------------------------------------------------------------------
// Kernel 1: fp32 -> bf16 conversion + exact fp32 row norms (warp per row).
// Also: x-rows init g_rowmin to +inf; block 0 resets per-batch tickets.
// ---------------------------------------------------------------------------
__global__ void prep_kernel(const float* __restrict__ src,
                            const float* __restrict__ tgt) {
    int warp = (blockIdx.x * blockDim.x + threadIdx.x) >> 5;
    int lane = threadIdx.x & 31;
    if (blockIdx.x == 0 && threadIdx.x < BB) g_done[threadIdx.x] = 0;
    const int total = BB * NN + BB * MM;
    if (warp >= total) return;

    const float* base; __nv_bfloat16* obase; float* onorm; int row;
    bool isx = warp < BB * NN;
    if (isx) { base = src; obase = g_xb16; onorm = g_xnorm; row = warp; }
    else     { base = tgt; obase = g_yb16; onorm = g_ynorm; row = warp - BB * NN; }

    const float4* p = (const float4*)(base + (long long)row * DD);
    float4 v0 = p[2 * lane];
    float4 v1 = p[2 * lane + 1];
    float s = v0.x * v0.x + v0.y * v0.y + v0.z * v0.z + v0.w * v0.w
            + v1.x * v1.x + v1.y * v1.y + v1.z * v1.z + v1.w * v1.w;

    __nv_bfloat162 h0 = __floats2bfloat162_rn(v0.x, v0.y);
    __nv_bfloat162 h1 = __floats2bfloat162_rn(v0.z, v0.w);
    __nv_bfloat162 h2 = __floats2bfloat162_rn(v1.x, v1.y);
    __nv_bfloat162 h3 = __floats2bfloat162_rn(v1.z, v1.w);
    uint4 o;
    o.x = *(uint32_t*)&h0; o.y = *(uint32_t*)&h1;
    o.z = *(uint32_t*)&h2; o.w = *(uint32_t*)&h3;
    ((uint4*)(obase + (long long)row * DD))[lane] = o;

#pragma unroll
    for (int off = 16; off > 0; off >>= 1) s += __shfl_down_sync(0xffffffffu, s, off);
    if (lane == 0) {
        onorm[row] = s;
        if (isx) g_rowmin[row] = 0x7F800000;   // +inf bits
    }
}

// ---------------------------------------------------------------------------
// Kernel 2: bf16 HMMA GEMM fused with row-min.
// One __syncthreads per tile; prefetch issued after the sync so it overlaps
// the MMA phase. k-loop manually software-pipelined (2-stage fragments).
// grid (32, 4) = 128 CTAs. Last CTA per batch reduces the batch mean.
// ---------------------------------------------------------------------------
__global__ __launch_bounds__(256, 1)
void mincost_kernel(float* __restrict__ out) {
    extern __shared__ __align__(1024) char smem[];
    __shared__ int ticket_s;
    __shared__ float red_s[8];
    uint32_t sb = smem_u32(smem);
    const int tid  = threadIdx.x;
    const int w    = tid >> 5;
    const int lane = tid & 31;
    const int b    = blockIdx.y;
    const int mgrp = blockIdx.x >> 1;
    const int half = blockIdx.x & 1;
    const int base_row = mgrp * 256;
    const int warpM = w >> 1;          // 0..3 (64 rows each)
    const int warpN = w & 1;           // 0..1 (32 cols each)
    const int groupID = lane >> 2;     // 0..7
    const int tig     = lane & 3;      // 0..3

    const __nv_bfloat16* xa  = g_xb16 + ((long long)b * NN + base_row) * DD;
    const __nv_bfloat16* yb  = g_yb16 + ((long long)b * MM + half * HALF) * DD;
    const float*         yng = g_ynorm + b * MM + half * HALF;

    // Issue A (256 rows) + B tile 0 + yn0 as cp.async group 0
#pragma unroll
    for (int u = 0; u < 32; ++u) {
        int c = tid + 256 * u;          // 8192 chunks of 16B
        int r = c >> 5, c16 = c & 31;
        cp_async16(sb + OFF_A + r * ASTRIDE + c16 * 16, xa + r * DD + c16 * 8);
    }
#pragma unroll
    for (int u = 0; u < 8; ++u) {
        int c = tid + 256 * u;          // 2048 chunks
        int r = c >> 5, c16 = c & 31;
        cp_async16(sb + OFF_B + r * ASTRIDE + c16 * 16, yb + r * DD + c16 * 8);
    }
    if (tid < TN) cp_async4(sb + OFF_YN + tid * 4, yng + tid);
    asm volatile("cp.async.commit_group;");

    // ldmatrix per-thread base addresses
    uint32_t aBase = sb + OFF_A + (uint32_t)(warpM * 64 + (lane & 15)) * ASTRIDE
                   + (uint32_t)((lane >> 4) * 16);
    uint32_t bBase = sb + OFF_B
                   + (uint32_t)(warpN * 32 + (lane & 7) + ((lane >> 4) & 1) * 8) * ASTRIDE
                   + (uint32_t)(((lane >> 3) & 1) * 16);

    float rmin[8];
#pragma unroll
    for (int i = 0; i < 8; ++i) rmin[i] = 3.4e38f;

    for (int jt = 0; jt < NTILES; ++jt) {
        const int s = jt & 1;

        // Tile jt's data (group committed last iteration) must be complete,
        // and this barrier also separates last iteration's reads of buffer
        // s^1 from the prefetch below that overwrites it.
        asm volatile("cp.async.wait_group 0;");
        __syncthreads();

        // Prefetch next tile into the buffer just freed; overlaps MMA below.
        if (jt + 1 < NTILES) {
            const __nv_bfloat16* yt = yb + (long long)(jt + 1) * TN * DD;
            uint32_t dstb = sb + OFF_B + (uint32_t)(s ^ 1) * BBUF;
#pragma unroll
            for (int u = 0; u < 8; ++u) {
                int c = tid + 256 * u;
                int r = c >> 5, c16 = c & 31;
                cp_async16(dstb + r * ASTRIDE + c16 * 16, yt + r * DD + c16 * 8);
            }
            if (tid < TN)
                cp_async4(sb + OFF_YN + (s ^ 1) * 256 + tid * 4,
                          yng + (jt + 1) * TN + tid);
            asm volatile("cp.async.commit_group;");
        }

        float acc[4][4][4];
#pragma unroll
        for (int mf = 0; mf < 4; ++mf)
#pragma unroll
            for (int nf = 0; nf < 4; ++nf)
#pragma unroll
                for (int i = 0; i < 4; ++i) acc[mf][nf][i] = 0.0f;

        const uint32_t bB = bBase + (uint32_t)s * BBUF;

        // Software-pipelined k-loop: load k+1 fragments while issuing k MMAs
        uint32_t afr[2][4][4], bfr[2][2][4];
#pragma unroll
        for (int mf = 0; mf < 4; ++mf)
            ldm_x4(afr[0][mf], aBase + (uint32_t)(mf * 16) * ASTRIDE);
#pragma unroll
        for (int p = 0; p < 2; ++p)
            ldm_x4(bfr[0][p], bB + (uint32_t)(p * 16) * ASTRIDE);

#pragma unroll
        for (int k = 0; k < 16; ++k) {
            const int cur = k & 1, nxt = cur ^ 1;
            if (k < 15) {
#pragma unroll
                for (int mf = 0; mf < 4; ++mf)
                    ldm_x4(afr[nxt][mf],
                           aBase + (uint32_t)(mf * 16) * ASTRIDE + (k + 1) * 32);
#pragma unroll
                for (int p = 0; p < 2; ++p)
                    ldm_x4(bfr[nxt][p],
                           bB + (uint32_t)(p * 16) * ASTRIDE + (k + 1) * 32);
            }
#pragma unroll
            for (int mf = 0; mf < 4; ++mf)
#pragma unroll
                for (int nf = 0; nf < 4; ++nf)
                    mma16816(acc[mf][nf], afr[cur][mf],
                             bfr[cur][nf >> 1][(nf & 1) * 2],
                             bfr[cur][nf >> 1][(nf & 1) * 2 + 1]);
        }

        // Fold tile into running per-thread row minima
        const float* ynp = (const float*)(smem + OFF_YN + s * 256);
#pragma unroll
        for (int nf = 0; nf < 4; ++nf) {
            float y0 = ynp[warpN * 32 + nf * 8 + tig * 2];
            float y1 = ynp[warpN * 32 + nf * 8 + tig * 2 + 1];
#pragma unroll
            for (int mf = 0; mf < 4; ++mf) {
                rmin[mf * 2] = fminf(rmin[mf * 2],
                    fminf(fmaf(-2.0f, acc[mf][nf][0], y0),
                          fmaf(-2.0f, acc[mf][nf][1], y1)));
                rmin[mf * 2 + 1] = fminf(rmin[mf * 2 + 1],
                    fminf(fmaf(-2.0f, acc[mf][nf][2], y0),
                          fmaf(-2.0f, acc[mf][nf][3], y1)));
            }
        }
    }

    // Reduce across the 4 threads sharing each row, then global atomicMin
#pragma unroll
    for (int i = 0; i < 8; ++i) {
        rmin[i] = fminf(rmin[i], __shfl_xor_sync(0xffffffffu, rmin[i], 1));
        rmin[i] = fminf(rmin[i], __shfl_xor_sync(0xffffffffu, rmin[i], 2));
    }
    if (tig == 0) {
#pragma unroll
        for (int mf = 0; mf < 4; ++mf)
#pragma unroll
            for (int h = 0; h < 2; ++h) {
                int row = base_row + warpM * 64 + mf * 16 + h * 8 + groupID;
                float xn = g_xnorm[b * NN + row];
                float cand = fmaxf(xn + rmin[mf * 2 + h], 0.0f);
                atomicMin(&g_rowmin[b * NN + row], __float_as_int(cand));
            }
    }

    // ----- ticketed tail: last CTA of this batch computes the batch mean -----
    __threadfence();           // publish atomicMin results
    __syncthreads();           // all warps' writebacks issued
    if (tid == 0) ticket_s = atomicAdd(&g_done[b], 1);
    __syncthreads();
    if (ticket_s == 2 * (NN / 256) - 1) {     // 31: all 32 CTAs of batch b done
        __threadfence();       // acquire: see all other CTAs' minima
        const int4* p = (const int4*)(g_rowmin + b * NN);
        float s = 0.0f;
        for (int i = tid; i < NN / 4; i += 256) {
            int4 v = p[i];
            s += __int_as_float(v.x) + __int_as_float(v.y)
               + __int_as_float(v.z) + __int_as_float(v.w);
        }
#pragma unroll
        for (int o = 16; o > 0; o >>= 1) s += __shfl_down_sync(0xffffffffu, s, o);
        if (lane == 0) red_s[w] = s;
        __syncthreads();
        if (tid == 0) {
            float t = 0.0f;
#pragma unroll
            for (int wv = 0; wv < 8; ++wv) t += red_s[wv];
            out[b] = t * (1.0f / (float)NN);
        }
    }
}

// ---------------------------------------------------------------------------
extern "C" void kernel_launch(void* const* d_in, const int* in_sizes, int n_in,
                              void* d_out, int out_size) {
    const float* src = (const float*)d_in[0];
    const float* tgt = (const float*)d_in[1];
    float* out = (float*)d_out;

    cudaFuncSetAttribute(mincost_kernel,
                         cudaFuncAttributeMaxDynamicSharedMemorySize, SMEM_TOTAL);

    prep_kernel<<<BB * (NN + MM) / 8, 256>>>(src, tgt);
    mincost_kernel<<<dim3(32, 4), 256, SMEM_TOTAL>>>(out);
}

// round 9
// speedup vs baseline: 10.7459x; 1.0421x over previous
#include <cuda_runtime.h>
#include <cuda_bf16.h>
#include <cstdint>

#define BB 4
#define NN 4096
#define MM 4096
#define DD 256

#define HALF (MM/2)           // 2048 targets per CTA
#define TILE_N 128            // targets per tile
#define NTILES (HALF/TILE_N)  // 16 tiles
#define NHALVES (2*NTILES)    // 32 k-half steps

// smem: A 256 rows x 512B (swizzled, no pad); B 2 bufs x (128 rows x 256B); yn 2x128 f32
#define OFF_A   0
#define A_BYTES (256*512)                 // 131072
#define OFF_B   A_BYTES
#define BHALF   (128*256)                 // 32768 per k-half buffer
#define OFF_YN  (OFF_B + 2*BHALF)         // 196608
#define SMEM_TOTAL (OFF_YN + 1024)        // 197632

// ---------------- device scratch (no allocs allowed) ----------------
__device__ __nv_bfloat16 g_xb16[BB * NN * DD];   // 8 MB
__device__ __nv_bfloat16 g_yb16[BB * MM * DD];   // 8 MB
__device__ float g_xnorm[BB * NN];
__device__ float g_ynorm[BB * MM];
__device__ int   g_rowmin[BB * NN];
__device__ int   g_done[BB];

// ---------------- helpers (plain-sm_100-compatible) ----------------
__device__ __forceinline__ uint32_t smem_u32(const void* p) {
    uint32_t a;
    asm("{ .reg .u64 t; cvta.to.shared.u64 t, %1; cvt.u32.u64 %0, t; }"
        : "=r"(a) : "l"(p));
    return a;
}
__device__ __forceinline__ void cp_async16(uint32_t dst, const void* src) {
    asm volatile("cp.async.cg.shared.global [%0], [%1], 16;" :: "r"(dst), "l"(src));
}
__device__ __forceinline__ void cp_async4(uint32_t dst, const void* src) {
    asm volatile("cp.async.ca.shared.global [%0], [%1], 4;" :: "r"(dst), "l"(src));
}
__device__ __forceinline__ void ldm_x4(uint32_t* r, uint32_t addr) {
    asm volatile("ldmatrix.sync.aligned.m8n8.x4.shared.b16 {%0,%1,%2,%3}, [%4];"
        : "=r"(r[0]), "=r"(r[1]), "=r"(r[2]), "=r"(r[3]) : "r"(addr));
}
__device__ __forceinline__ void mma16816(float* c, const uint32_t* a,
                                         uint32_t b0, uint32_t b1) {
    asm volatile(
        "mma.sync.aligned.m16n8k16.row.col.f32.bf16.bf16.f32 "
        "{%0,%1,%2,%3}, {%4,%5,%6,%7}, {%8,%9}, {%0,%1,%2,%3};"
        : "+f"(c[0]), "+f"(c[1]), "+f"(c[2]), "+f"(c[3])
        : "r"(a[0]), "r"(a[1]), "r"(a[2]), "r"(a[3]), "r"(b0), "r"(b1));
}

// ---------------------------------------------------------------------------
// Kernel 1: fp32 -> bf16 + exact fp32 row norms (warp per row); init rowmin.
// ---------------------------------------------------------------------------
__global__ void prep_kernel(const float* __restrict__ src,
                            const float* __restrict__ tgt) {
    int warp = (blockIdx.x * blockDim.x + threadIdx.x) >> 5;
    int lane = threadIdx.x & 31;
    if (blockIdx.x == 0 && threadIdx.x < BB) g_done[threadIdx.x] = 0;
    const int total = BB * NN + BB * MM;
    if (warp >= total) return;

    const float* base; __nv_bfloat16* obase; float* onorm; int row;
    bool isx = warp < BB * NN;
    if (isx) { base = src; obase = g_xb16; onorm = g_xnorm; row = warp; }
    else     { base = tgt; obase = g_yb16; onorm = g_ynorm; row = warp - BB * NN; }

    const float4* p = (const float4*)(base + (long long)row * DD);
    float4 v0 = p[2 * lane];
    float4 v1 = p[2 * lane + 1];
    float s = v0.x * v0.x + v0.y * v0.y + v0.z * v0.z + v0.w * v0.w
            + v1.x * v1.x + v1.y * v1.y + v1.z * v1.z + v1.w * v1.w;

    __nv_bfloat162 h0 = __floats2bfloat162_rn(v0.x, v0.y);
    __nv_bfloat162 h1 = __floats2bfloat162_rn(v0.z, v0.w);
    __nv_bfloat162 h2 = __floats2bfloat162_rn(v1.x, v1.y);
    __nv_bfloat162 h3 = __floats2bfloat162_rn(v1.z, v1.w);
    uint4 o;
    o.x = *(uint32_t*)&h0; o.y = *(uint32_t*)&h1;
    o.z = *(uint32_t*)&h2; o.w = *(uint32_t*)&h3;
    ((uint4*)(obase + (long long)row * DD))[lane] = o;

#pragma unroll
    for (int off = 16; off > 0; off >>= 1) s += __shfl_down_sync(0xffffffffu, s, off);
    if (lane == 0) {
        onorm[row] = s;
        if (isx) g_rowmin[row] = 0x7F800000;
    }
}

// ---------------------------------------------------------------------------
// Kernel 2: bf16 HMMA GEMM + row-min. Warp tile 64x64 (4Mx2N warps).
// CTA = 256 rows x 2048 targets, 16 tiles of 128 targets, B pipelined at
// k-half (128-k) granularity: 32 half-steps, 2 x 32KB buffers.
// XOR-swizzled smem (no padding). grid (32,4).
// ---------------------------------------------------------------------------
__global__ __launch_bounds__(256, 1)
void mincost_kernel(float* __restrict__ out) {
    extern __shared__ __align__(1024) char smem[];
    __shared__ int ticket_s;
    __shared__ float red_s[8];
    uint32_t sb = smem_u32(smem);
    const int tid  = threadIdx.x;
    const int w    = tid >> 5;
    const int lane = tid & 31;
    const int b    = blockIdx.y;
    const int mgrp = blockIdx.x >> 1;
    const int half = blockIdx.x & 1;
    const int base_row = mgrp * 256;
    const int warpM = w >> 1;          // 0..3 (64 rows)
    const int warpN = w & 1;           // 0..1 (64 targets)
    const int groupID = lane >> 2;
    const int tig     = lane & 3;

    const __nv_bfloat16* xa  = g_xb16 + ((long long)b * NN + base_row) * DD;
    const __nv_bfloat16* yb  = g_yb16 + ((long long)b * MM + half * HALF) * DD;
    const float*         yng = g_ynorm + b * MM + half * HALF;

    // ---- initial loads: A (swizzled) + B k-half 0 of tile 0 + yn[0] ----
#pragma unroll
    for (int u = 0; u < 32; ++u) {
        int c = tid + 256 * u;              // 8192 chunks of 16B
        int r = c >> 5, c16 = c & 31;
        cp_async16(sb + OFF_A + r * 512 + ((c16 ^ (r & 7)) << 4),
                   xa + r * DD + c16 * 8);
    }
#pragma unroll
    for (int u = 0; u < 8; ++u) {
        int c = tid + 256 * u;              // 2048 chunks (128 rows x 16)
        int r = c >> 4, c16 = c & 15;
        cp_async16(sb + OFF_B + r * 256 + ((c16 ^ (r & 7)) << 4),
                   yb + r * DD + c16 * 8);
    }
    if (tid < TILE_N) cp_async4(sb + OFF_YN + tid * 4, yng + tid);
    asm volatile("cp.async.commit_group;");

    // per-lane fragment addressing (XOR swizzle folded in per k-step)
    const int rowA = warpM * 64 + (lane & 15);
    const int hiA  = lane >> 4;                 // 0/1
    const int rowB = warpN * 64 + (lane & 7) + ((lane >> 4) & 1) * 8;
    const int hiB  = (lane >> 3) & 1;
    const int rm   = lane & 7;                  // = rowA&7 = rowB&7
    const uint32_t aRow = sb + OFF_A + (uint32_t)rowA * 512;

    float rmin[8];
#pragma unroll
    for (int i = 0; i < 8; ++i) rmin[i] = 3.4e38f;

    float acc[4][8][4];

    for (int h = 0; h < NHALVES; ++h) {
        const int buf   = h & 1;
        const int khalf = h & 1;
        const int jt    = h >> 1;

        asm volatile("cp.async.wait_group 0;");
        __syncthreads();

        // prefetch k-half h+1 into the other buffer (overlaps compute below)
        if (h + 1 < NHALVES) {
            const int jn = (h + 1) >> 1, kn = (h + 1) & 1;
            const __nv_bfloat16* yt = yb + (long long)jn * TILE_N * DD + kn * 128;
            uint32_t dstb = sb + OFF_B + (uint32_t)(buf ^ 1) * BHALF;
#pragma unroll
            for (int u = 0; u < 8; ++u) {
                int c = tid + 256 * u;
                int r = c >> 4, c16 = c & 15;
                cp_async16(dstb + r * 256 + ((c16 ^ (r & 7)) << 4),
                           yt + r * DD + c16 * 8);
            }
            if (kn == 0 && tid < TILE_N)
                cp_async4(sb + OFF_YN + (jn & 1) * 512 + tid * 4,
                          yng + jn * TILE_N + tid);
            asm volatile("cp.async.commit_group;");
        }

        if (khalf == 0) {
#pragma unroll
            for (int mf = 0; mf < 4; ++mf)
#pragma unroll
                for (int nf = 0; nf < 8; ++nf)
#pragma unroll
                    for (int i = 0; i < 4; ++i) acc[mf][nf][i] = 0.0f;
        }

        const uint32_t bRow = sb + OFF_B + (uint32_t)buf * BHALF
                            + (uint32_t)rowB * 256;
#pragma unroll
        for (int kk = 0; kk < 8; ++kk) {
            const int ks = khalf * 8 + kk;                  // abs k-step 0..15
            const uint32_t ac = (uint32_t)(((2 * ks + hiA) ^ rm) << 4);
            const uint32_t bc = (uint32_t)(((2 * kk + hiB) ^ rm) << 4);
            uint32_t afr[4][4], bfr[4][4];
#pragma unroll
            for (int mf = 0; mf < 4; ++mf)
                ldm_x4(afr[mf], aRow + (uint32_t)(mf * 16 * 512) + ac);
#pragma unroll
            for (int nf2 = 0; nf2 < 4; ++nf2)
                ldm_x4(bfr[nf2], bRow + (uint32_t)(nf2 * 16 * 256) + bc);
#pragma unroll
            for (int mf = 0; mf < 4; ++mf)
#pragma unroll
                for (int nf2 = 0; nf2 < 4; ++nf2)
#pragma unroll
                    for (int g = 0; g < 2; ++g)
                        mma16816(acc[mf][nf2 * 2 + g], afr[mf],
                                 bfr[nf2][g * 2], bfr[nf2][g * 2 + 1]);
        }

        // fold at tile end (after k-hi half)
        if (khalf == 1) {
            const float* ynp = (const float*)(smem + OFF_YN + (jt & 1) * 512);
#pragma unroll
            for (int nf = 0; nf < 8; ++nf) {
                float y0 = ynp[warpN * 64 + nf * 8 + tig * 2];
                float y1 = ynp[warpN * 64 + nf * 8 + tig * 2 + 1];
#pragma unroll
                for (int mf = 0; mf < 4; ++mf) {
                    rmin[mf * 2] = fminf(rmin[mf * 2],
                        fminf(fmaf(-2.0f, acc[mf][nf][0], y0),
                              fmaf(-2.0f, acc[mf][nf][1], y1)));
                    rmin[mf * 2 + 1] = fminf(rmin[mf * 2 + 1],
                        fminf(fmaf(-2.0f, acc[mf][nf][2], y0),
                              fmaf(-2.0f, acc[mf][nf][3], y1)));
                }
            }
        }
    }

    // reduce over the 4 threads sharing each row, then global atomicMin
#pragma unroll
    for (int i = 0; i < 8; ++i) {
        rmin[i] = fminf(rmin[i], __shfl_xor_sync(0xffffffffu, rmin[i], 1));
        rmin[i] = fminf(rmin[i], __shfl_xor_sync(0xffffffffu, rmin[i], 2));
    }
    if (tig == 0) {
#pragma unroll
        for (int mf = 0; mf < 4; ++mf)
#pragma unroll
            for (int h8 = 0; h8 < 2; ++h8) {
                int row = base_row + warpM * 64 + mf * 16 + h8 * 8 + groupID;
                float xn = g_xnorm[b * NN + row];
                float cand = fmaxf(xn + rmin[mf * 2 + h8], 0.0f);
                atomicMin(&g_rowmin[b * NN + row], __float_as_int(cand));
            }
    }

    // ----- ticketed tail: last CTA of this batch computes the batch mean -----
    __threadfence();
    __syncthreads();
    if (tid == 0) ticket_s = atomicAdd(&g_done[b], 1);
    __syncthreads();
    if (ticket_s == 2 * (NN / 256) - 1) {
        __threadfence();
        const int4* p = (const int4*)(g_rowmin + b * NN);
        float s = 0.0f;
        for (int i = tid; i < NN / 4; i += 256) {
            int4 v = p[i];
            s += __int_as_float(v.x) + __int_as_float(v.y)
               + __int_as_float(v.z) + __int_as_float(v.w);
        }
#pragma unroll
        for (int o = 16; o > 0; o >>= 1) s += __shfl_down_sync(0xffffffffu, s, o);
        if (lane == 0) red_s[w] = s;
        __syncthreads();
        if (tid == 0) {
            float t = 0.0f;
#pragma unroll
            for (int wv = 0; wv < 8; ++wv) t += red_s[wv];
            out[b] = t * (1.0f / (float)NN);
        }
    }
}

// ---------------------------------------------------------------------------
extern "C" void kernel_launch(void* const* d_in, const int* in_sizes, int n_in,
                              void* d_out, int out_size) {
    const float* src = (const float*)d_in[0];
    const float* tgt = (const float*)d_in[1];
    float* out = (float*)d_out;

    cudaFuncSetAttribute(mincost_kernel,
                         cudaFuncAttributeMaxDynamicSharedMemorySize, SMEM_TOTAL);

    prep_kernel<<<BB * (NN + MM) / 8, 256>>>(src, tgt);
    mincost_kernel<<<dim3(32, 4), 256, SMEM_TOTAL>>>(out);
}